// round 4
// baseline (speedup 1.0000x reference)
#include <cuda_runtime.h>
#include <cstddef>

#define HH 16
#define DD 1024
#define KD 64
#define NN 4096
#define MM 4096

// Scratch (static __device__ arrays: the allowed workaround for no-malloc rule)
static __device__ float g_Q[(size_t)HH * NN * KD];   // [h][n][64]
static __device__ float g_K[(size_t)HH * MM * KD];   // [h][m][64]
static __device__ float g_V[(size_t)HH * MM * KD];   // [h][m][64]
static __device__ float g_O[(size_t)NN * (HH * KD)]; // [n][h*64+v]

// ---------------------------------------------------------------------------
// Generic fp32 GEMM: C_tile[128 x 64] = A[128 x K] * W[K x 64]
// blockIdx.x = row tile, blockIdx.y = head / column-block (selected via strides)
// ---------------------------------------------------------------------------
__global__ __launch_bounds__(256) void gemm128x64(
    const float* __restrict__ A, int lda,
    const float* __restrict__ W, long wStride, int ldw,
    float* __restrict__ C, long cStride, int ldc, int K)
{
    __shared__ float As[128 * 33];  // A tile, rows padded to 33 (bank-conflict free)
    __shared__ float Ws[32 * 64];   // W tile

    const int tid = threadIdx.x;
    const int tx = tid & 15;        // 16 col-threads
    const int ty = tid >> 4;        // 16 row-threads
    const int row0 = blockIdx.x * 128;
    const float* Wp = W + (long)blockIdx.y * wStride;
    float*       Cp = C + (long)blockIdx.y * cStride;

    float acc[8][4];
#pragma unroll
    for (int i = 0; i < 8; i++)
#pragma unroll
        for (int j = 0; j < 4; j++) acc[i][j] = 0.0f;

    for (int kt = 0; kt < K; kt += 32) {
        // Load A tile 128x32 (coalesced float4, scalar store into padded smem)
#pragma unroll
        for (int u = 0; u < 4; u++) {
            int idx = tid + u * 256;         // 0..1023 float4 slots
            int r   = idx >> 3;              // 0..127
            int kv  = idx & 7;               // 0..7
            float4 v = *(const float4*)(A + (size_t)(row0 + r) * lda + kt + kv * 4);
            As[r * 33 + kv * 4 + 0] = v.x;
            As[r * 33 + kv * 4 + 1] = v.y;
            As[r * 33 + kv * 4 + 2] = v.z;
            As[r * 33 + kv * 4 + 3] = v.w;
        }
        // Load W tile 32x64
#pragma unroll
        for (int u = 0; u < 2; u++) {
            int idx = tid + u * 256;         // 0..511 float4 slots
            int kk  = idx >> 4;              // 0..31
            int cv  = idx & 15;              // 0..15
            float4 v = *(const float4*)(Wp + (size_t)(kt + kk) * ldw + cv * 4);
            *(float4*)(Ws + kk * 64 + cv * 4) = v;
        }
        __syncthreads();

#pragma unroll 8
        for (int kk = 0; kk < 32; kk++) {
            float a[8], w[4];
#pragma unroll
            for (int i = 0; i < 8; i++) a[i] = As[(ty + 16 * i) * 33 + kk];
#pragma unroll
            for (int j = 0; j < 4; j++) w[j] = Ws[kk * 64 + tx + 16 * j];
#pragma unroll
            for (int i = 0; i < 8; i++)
#pragma unroll
                for (int j = 0; j < 4; j++)
                    acc[i][j] = fmaf(a[i], w[j], acc[i][j]);
        }
        __syncthreads();
    }

#pragma unroll
    for (int i = 0; i < 8; i++)
#pragma unroll
        for (int j = 0; j < 4; j++)
            Cp[(size_t)(row0 + ty + 16 * i) * ldc + tx + 16 * j] = acc[i][j];
}

// ---------------------------------------------------------------------------
// Flash attention, fp32. One CTA: head h, query tile of 128 rows.
// BM=128, BN=64, 256 threads, 8x4 strided register tiles.
// Masked logits = -1e30 (self-correcting online softmax; final weights exactly 0
// once any real logit is seen, matching the reference's -inf behavior).
// ---------------------------------------------------------------------------
__global__ __launch_bounds__(256, 2) void attn_kernel(const int* __restrict__ mask)
{
    extern __shared__ float sm[];
    float* Qs = sm;                 // 128 x 65
    float* Ks = Qs + 128 * 65;      // 64 x 65
    float* Vs = Ks + 64 * 65;       // 64 x 64
    float* Ps = Vs + 64 * 64;       // 128 x 65

    const int tid = threadIdx.x;
    const int tx  = tid & 15;
    const int ty  = tid >> 4;
    const int h   = blockIdx.x;         // heads fastest -> mask tile L2 reuse
    const int n0  = blockIdx.y * 128;

    const float* Qh = g_Q + (size_t)h * NN * KD;
    const float* Kh = g_K + (size_t)h * MM * KD;
    const float* Vh = g_V + (size_t)h * MM * KD;

    // Load Q tile (128x64), padded rows
#pragma unroll
    for (int u = 0; u < 8; u++) {
        int idx = tid + u * 256;       // 0..2047 float4 slots
        int r   = idx >> 4;            // 0..127
        int kv  = idx & 15;            // 0..15
        float4 v = *(const float4*)(Qh + (size_t)(n0 + r) * KD + kv * 4);
        Qs[r * 65 + kv * 4 + 0] = v.x;
        Qs[r * 65 + kv * 4 + 1] = v.y;
        Qs[r * 65 + kv * 4 + 2] = v.z;
        Qs[r * 65 + kv * 4 + 3] = v.w;
    }

    float mrow[8], lrow[8], o[8][4];
#pragma unroll
    for (int i = 0; i < 8; i++) {
        mrow[i] = -1e30f;
        lrow[i] = 0.0f;
#pragma unroll
        for (int j = 0; j < 4; j++) o[i][j] = 0.0f;
    }

    for (int mt = 0; mt < MM; mt += 64) {
        // Load K (padded) and V (unpadded) tiles 64x64
#pragma unroll
        for (int u = 0; u < 4; u++) {
            int idx = tid + u * 256;   // 0..1023 float4 slots
            int j   = idx >> 4;        // 0..63
            int kv  = idx & 15;
            float4 kval = *(const float4*)(Kh + (size_t)(mt + j) * KD + kv * 4);
            Ks[j * 65 + kv * 4 + 0] = kval.x;
            Ks[j * 65 + kv * 4 + 1] = kval.y;
            Ks[j * 65 + kv * 4 + 2] = kval.z;
            Ks[j * 65 + kv * 4 + 3] = kval.w;
            float4 vval = *(const float4*)(Vh + (size_t)(mt + j) * KD + kv * 4);
            *(float4*)(Vs + j * 64 + kv * 4) = vval;
        }
        __syncthreads();

        // S = Q K^T  (128x64 tile, fp32)
        float s[8][4];
#pragma unroll
        for (int i = 0; i < 8; i++)
#pragma unroll
            for (int j = 0; j < 4; j++) s[i][j] = 0.0f;

#pragma unroll 4
        for (int kd = 0; kd < 64; kd++) {
            float q[8], k[4];
#pragma unroll
            for (int i = 0; i < 8; i++) q[i] = Qs[(ty + 16 * i) * 65 + kd];
#pragma unroll
            for (int j = 0; j < 4; j++) k[j] = Ks[(tx + 16 * j) * 65 + kd];
#pragma unroll
            for (int i = 0; i < 8; i++)
#pragma unroll
                for (int j = 0; j < 4; j++)
                    s[i][j] = fmaf(q[i], k[j], s[i][j]);
        }

        // Apply mask
#pragma unroll
        for (int i = 0; i < 8; i++) {
            const int* mp = mask + (size_t)(n0 + ty + 16 * i) * MM + mt + tx;
#pragma unroll
            for (int j = 0; j < 4; j++)
                if (mp[16 * j] == 0) s[i][j] = -1e30f;
        }

        // Online softmax (row = 16 lanes: shfl_xor 1..8 stays in 16-lane halves)
#pragma unroll
        for (int i = 0; i < 8; i++) {
            float mx = fmaxf(fmaxf(s[i][0], s[i][1]), fmaxf(s[i][2], s[i][3]));
            mx = fmaxf(mx, __shfl_xor_sync(0xffffffffu, mx, 1));
            mx = fmaxf(mx, __shfl_xor_sync(0xffffffffu, mx, 2));
            mx = fmaxf(mx, __shfl_xor_sync(0xffffffffu, mx, 4));
            mx = fmaxf(mx, __shfl_xor_sync(0xffffffffu, mx, 8));
            float mnew = fmaxf(mrow[i], mx);
            float sc   = __expf(mrow[i] - mnew);
            mrow[i] = mnew;
            float rs = 0.0f;
#pragma unroll
            for (int j = 0; j < 4; j++) {
                float p = __expf(s[i][j] - mnew);
                s[i][j] = p;
                rs += p;
            }
            rs += __shfl_xor_sync(0xffffffffu, rs, 1);
            rs += __shfl_xor_sync(0xffffffffu, rs, 2);
            rs += __shfl_xor_sync(0xffffffffu, rs, 4);
            rs += __shfl_xor_sync(0xffffffffu, rs, 8);
            lrow[i] = lrow[i] * sc + rs;
#pragma unroll
            for (int j = 0; j < 4; j++) {
                o[i][j] *= sc;
                Ps[(ty + 16 * i) * 65 + tx + 16 * j] = s[i][j];
            }
        }
        __syncthreads();

        // O += P V
#pragma unroll 4
        for (int jm = 0; jm < 64; jm++) {
            float p[8], v[4];
#pragma unroll
            for (int i = 0; i < 8; i++) p[i] = Ps[(ty + 16 * i) * 65 + jm];
#pragma unroll
            for (int j = 0; j < 4; j++) v[j] = Vs[jm * 64 + tx + 16 * j];
#pragma unroll
            for (int i = 0; i < 8; i++)
#pragma unroll
                for (int j = 0; j < 4; j++)
                    o[i][j] = fmaf(p[i], v[j], o[i][j]);
        }
        __syncthreads();
    }

    // Write O[n][h*64+v] = o / l
    float* Oh = g_O + (size_t)h * KD;
#pragma unroll
    for (int i = 0; i < 8; i++) {
        float inv = 1.0f / lrow[i];
#pragma unroll
        for (int j = 0; j < 4; j++)
            Oh[(size_t)(n0 + ty + 16 * i) * (HH * KD) + tx + 16 * j] = o[i][j] * inv;
    }
}

// ---------------------------------------------------------------------------
extern "C" void kernel_launch(void* const* d_in, const int* in_sizes, int n_in,
                              void* d_out, int out_size)
{
    const float* X    = (const float*)d_in[0];
    const float* Mm   = (const float*)d_in[1];
    const int*   mask = (const int*)  d_in[2];
    const float* Wq   = (const float*)d_in[3];
    const float* Wk   = (const float*)d_in[4];
    const float* Wv   = (const float*)d_in[5];
    const float* Wo   = (const float*)d_in[6];
    float*       Y    = (float*)d_out;

    float *qp, *kp, *vp, *op;
    cudaGetSymbolAddress((void**)&qp, g_Q);
    cudaGetSymbolAddress((void**)&kp, g_K);
    cudaGetSymbolAddress((void**)&vp, g_V);
    cudaGetSymbolAddress((void**)&op, g_O);

    const int SMEM_ATTN = (128 * 65 + 64 * 65 + 64 * 64 + 128 * 65) * (int)sizeof(float);
    cudaFuncSetAttribute(attn_kernel, cudaFuncAttributeMaxDynamicSharedMemorySize, SMEM_ATTN);

    dim3 blk(256);
    // Q = X @ Wq_h   (per head h = blockIdx.y)
    gemm128x64<<<dim3(NN / 128, HH), blk>>>(X,  DD, Wq, (long)DD * KD, KD, qp, (long)NN * KD, KD, DD);
    // K = M @ Wk_h
    gemm128x64<<<dim3(MM / 128, HH), blk>>>(Mm, DD, Wk, (long)DD * KD, KD, kp, (long)MM * KD, KD, DD);
    // V = M @ Wv_h
    gemm128x64<<<dim3(MM / 128, HH), blk>>>(Mm, DD, Wv, (long)DD * KD, KD, vp, (long)MM * KD, KD, DD);
    // Attention (grid: heads fastest for mask L2 reuse)
    attn_kernel<<<dim3(HH, NN / 128), blk, SMEM_ATTN>>>(mask);
    // Y = O @ Wo_flat   (Wo [H,Vd,D] is exactly the [1024,1024] flat operand;
    //                    blockIdx.y = output column block of 64)
    gemm128x64<<<dim3(NN / 128, (HH * KD) / 64), blk>>>(op, HH * KD, Wo, (long)KD, HH * KD, Y, (long)KD, HH * KD, DD);
}

// round 5
// speedup vs baseline: 1.1327x; 1.1327x over previous
#include <cuda_runtime.h>
#include <cstddef>

#define HH 16
#define DD 1024
#define KD 64
#define NN 4096
#define MM 4096

// Scratch (static __device__ arrays: the allowed workaround for no-malloc rule)
static __device__ float g_Q[(size_t)HH * NN * KD];   // [h][n][64]
static __device__ float g_K[(size_t)HH * MM * KD];   // [h][m][64]
static __device__ float g_V[(size_t)HH * MM * KD];   // [h][m][64]
static __device__ float g_O[(size_t)NN * (HH * KD)]; // [n][h*64+v]

typedef unsigned long long u64;

// ---- packed fp32x2 helpers (FFMA2 path: only reachable via PTX) ----------
__device__ __forceinline__ u64 dup2(float x) {
    u64 r; unsigned xi = __float_as_uint(x);
    asm("mov.b64 %0, {%1, %1};" : "=l"(r) : "r"(xi));
    return r;
}
__device__ __forceinline__ void ffma2(u64& d, u64 a, u64 b) {
    asm("fma.rn.f32x2 %0, %1, %2, %0;" : "+l"(d) : "l"(a), "l"(b));
}
__device__ __forceinline__ void fmul2(u64& d, u64 b) {
    asm("mul.rn.f32x2 %0, %0, %1;" : "+l"(d) : "l"(b));
}
__device__ __forceinline__ float f2lo(u64 v) { return __uint_as_float((unsigned)v); }
__device__ __forceinline__ float f2hi(u64 v) { return __uint_as_float((unsigned)(v >> 32)); }

// ---------------------------------------------------------------------------
// fp32 GEMM: C_tile[128 x 64] = A[128 x K] * W[K x 64]
// A tile stored kd-major (transposed) in smem -> contiguous row-pair LDS.128
// (warp-broadcast). W tile row-major -> one conflict-free LDS.128 per kk.
// Inner product uses fma.rn.f32x2 with accumulators packed across row pairs.
// ---------------------------------------------------------------------------
__global__ __launch_bounds__(256) void gemm128x64(
    const float* __restrict__ A, int lda,
    const float* __restrict__ W, long wStride, int ldw,
    float* __restrict__ C, long cStride, int ldc, int K)
{
    __shared__ float At[32 * 132];   // [kk][row], stride 132 (16B-aligned rows)
    __shared__ float Ws[32 * 68];    // [kk][col], stride 68

    const int tid = threadIdx.x;
    const int tx  = tid & 15;        // col block: cols c0..c0+3
    const int ty  = tid >> 4;        // row block: rows r0..r0+7
    const int c0  = tx * 4;
    const int r0  = ty * 8;
    const int row0 = blockIdx.x * 128;
    const float* Wp = W + (long)blockIdx.y * wStride;
    float*       Cp = C + (long)blockIdx.y * cStride;

    u64 acc[4][4];                   // [row-pair][col], lanes = rows (2i2, 2i2+1)
#pragma unroll
    for (int i = 0; i < 4; i++)
#pragma unroll
        for (int j = 0; j < 4; j++) acc[i][j] = 0ull;

    for (int kt = 0; kt < K; kt += 32) {
        // A tile 128x32, scatter transposed
#pragma unroll
        for (int u = 0; u < 4; u++) {
            int idx = tid + u * 256;        // 1024 float4 slots
            int r   = idx >> 3;             // 0..127
            int kv  = idx & 7;              // 0..7
            float4 v = *(const float4*)(A + (size_t)(row0 + r) * lda + kt + kv * 4);
            At[(kv * 4 + 0) * 132 + r] = v.x;
            At[(kv * 4 + 1) * 132 + r] = v.y;
            At[(kv * 4 + 2) * 132 + r] = v.z;
            At[(kv * 4 + 3) * 132 + r] = v.w;
        }
        // W tile 32x64, vector store
#pragma unroll
        for (int u = 0; u < 2; u++) {
            int idx = tid + u * 256;        // 512 float4 slots
            int kk  = idx >> 4;             // 0..31
            int cv  = idx & 15;             // 0..15
            *(float4*)(Ws + kk * 68 + cv * 4) =
                *(const float4*)(Wp + (size_t)(kt + kk) * ldw + cv * 4);
        }
        __syncthreads();

#pragma unroll 2
        for (int kk = 0; kk < 32; kk++) {
            ulonglong2 qa = *(const ulonglong2*)(At + kk * 132 + r0);      // rows r0..r0+3
            ulonglong2 qb = *(const ulonglong2*)(At + kk * 132 + r0 + 4);  // rows r0+4..r0+7
            float4 wf = *(const float4*)(Ws + kk * 68 + c0);
            u64 w0 = dup2(wf.x), w1 = dup2(wf.y), w2 = dup2(wf.z), w3 = dup2(wf.w);
            ffma2(acc[0][0], qa.x, w0); ffma2(acc[0][1], qa.x, w1);
            ffma2(acc[0][2], qa.x, w2); ffma2(acc[0][3], qa.x, w3);
            ffma2(acc[1][0], qa.y, w0); ffma2(acc[1][1], qa.y, w1);
            ffma2(acc[1][2], qa.y, w2); ffma2(acc[1][3], qa.y, w3);
            ffma2(acc[2][0], qb.x, w0); ffma2(acc[2][1], qb.x, w1);
            ffma2(acc[2][2], qb.x, w2); ffma2(acc[2][3], qb.x, w3);
            ffma2(acc[3][0], qb.y, w0); ffma2(acc[3][1], qb.y, w1);
            ffma2(acc[3][2], qb.y, w2); ffma2(acc[3][3], qb.y, w3);
        }
        __syncthreads();
    }

#pragma unroll
    for (int i2 = 0; i2 < 4; i2++) {
        *(float4*)(Cp + (size_t)(row0 + r0 + 2 * i2) * ldc + c0) =
            make_float4(f2lo(acc[i2][0]), f2lo(acc[i2][1]), f2lo(acc[i2][2]), f2lo(acc[i2][3]));
        *(float4*)(Cp + (size_t)(row0 + r0 + 2 * i2 + 1) * ldc + c0) =
            make_float4(f2hi(acc[i2][0]), f2hi(acc[i2][1]), f2hi(acc[i2][2]), f2hi(acc[i2][3]));
    }
}

// ---------------------------------------------------------------------------
// Flash attention fp32, BM=128 x BN=64, 256 threads.
// Thread tile: rows r0..r0+7 (contiguous), cols c0..c0+3 (contiguous).
// Q,K stored kd-major in smem (transposed) -> vector broadcast loads.
// QK^T: accumulators packed across row pairs; PV: packed across col pairs.
// ---------------------------------------------------------------------------
__global__ __launch_bounds__(256, 2) void attn_kernel(const int* __restrict__ mask)
{
    extern __shared__ float sm[];
    float* Qt = sm;                  // [64 kd][132]   (rows, pad->16B aligned)
    float* Kt = Qt + 64 * 132;       // [64 kd][68]    (cols)
    float* Vs = Kt + 64 * 68;        // [64 jm][68]    (row-major)
    float* Ps = Vs + 64 * 68;        // [128 row][68]

    const int tid = threadIdx.x;
    const int tx  = tid & 15;
    const int ty  = tid >> 4;
    const int c0  = tx * 4;
    const int r0  = ty * 8;
    const int h   = blockIdx.x;      // heads fastest -> mask tile L2 reuse
    const int n0  = blockIdx.y * 128;

    const float* Qh = g_Q + (size_t)h * NN * KD;
    const float* Kh = g_K + (size_t)h * MM * KD;
    const float* Vh = g_V + (size_t)h * MM * KD;

    // Load Q tile 128x64, store kd-major
#pragma unroll
    for (int u = 0; u < 8; u++) {
        int idx = tid + u * 256;     // 2048 float4 slots
        int r   = idx >> 4;          // 0..127
        int kv  = idx & 15;          // 0..15
        float4 v = *(const float4*)(Qh + (size_t)(n0 + r) * KD + kv * 4);
        Qt[(kv * 4 + 0) * 132 + r] = v.x;
        Qt[(kv * 4 + 1) * 132 + r] = v.y;
        Qt[(kv * 4 + 2) * 132 + r] = v.z;
        Qt[(kv * 4 + 3) * 132 + r] = v.w;
    }

    float mrow[8], lrow[8];
    u64 o2[8][2];                    // [row][col-pair], lanes = cols (2j, 2j+1)
#pragma unroll
    for (int i = 0; i < 8; i++) {
        mrow[i] = -1e30f; lrow[i] = 0.0f;
        o2[i][0] = 0ull; o2[i][1] = 0ull;
    }

    for (int mt = 0; mt < MM; mt += 64) {
        __syncthreads();             // prior PV readers of Vs / QK readers of Kt done

        // Load K (kd-major) and V (row-major) 64x64 tiles
#pragma unroll
        for (int u = 0; u < 4; u++) {
            int idx = tid + u * 256; // 1024 float4 slots
            int j   = idx >> 4;      // 0..63
            int kv  = idx & 15;
            float4 kf = *(const float4*)(Kh + (size_t)(mt + j) * KD + kv * 4);
            Kt[(kv * 4 + 0) * 68 + j] = kf.x;
            Kt[(kv * 4 + 1) * 68 + j] = kf.y;
            Kt[(kv * 4 + 2) * 68 + j] = kf.z;
            Kt[(kv * 4 + 3) * 68 + j] = kf.w;
            *(float4*)(Vs + j * 68 + kv * 4) =
                *(const float4*)(Vh + (size_t)(mt + j) * KD + kv * 4);
        }
        __syncthreads();

        // ---- S = Q K^T (row-pair packed) ----
        u64 s2[4][4];                // [row-pair][col]
#pragma unroll
        for (int i = 0; i < 4; i++)
#pragma unroll
            for (int j = 0; j < 4; j++) s2[i][j] = 0ull;

#pragma unroll 2
        for (int kd = 0; kd < 64; kd++) {
            ulonglong2 qa = *(const ulonglong2*)(Qt + kd * 132 + r0);
            ulonglong2 qb = *(const ulonglong2*)(Qt + kd * 132 + r0 + 4);
            float4 kf = *(const float4*)(Kt + kd * 68 + c0);
            u64 k0 = dup2(kf.x), k1 = dup2(kf.y), k2 = dup2(kf.z), k3 = dup2(kf.w);
            ffma2(s2[0][0], qa.x, k0); ffma2(s2[0][1], qa.x, k1);
            ffma2(s2[0][2], qa.x, k2); ffma2(s2[0][3], qa.x, k3);
            ffma2(s2[1][0], qa.y, k0); ffma2(s2[1][1], qa.y, k1);
            ffma2(s2[1][2], qa.y, k2); ffma2(s2[1][3], qa.y, k3);
            ffma2(s2[2][0], qb.x, k0); ffma2(s2[2][1], qb.x, k1);
            ffma2(s2[2][2], qb.x, k2); ffma2(s2[2][3], qb.x, k3);
            ffma2(s2[3][0], qb.y, k0); ffma2(s2[3][1], qb.y, k1);
            ffma2(s2[3][2], qb.y, k2); ffma2(s2[3][3], qb.y, k3);
        }

        // ---- mask + online softmax ----
#pragma unroll
        for (int i2 = 0; i2 < 4; i2++) {
#pragma unroll
            for (int sub = 0; sub < 2; sub++) {
                const int i = i2 * 2 + sub;
                const int4 mi = *(const int4*)(mask + (size_t)(n0 + r0 + i) * MM + mt + c0);
                float v0 = sub ? f2hi(s2[i2][0]) : f2lo(s2[i2][0]);
                float v1 = sub ? f2hi(s2[i2][1]) : f2lo(s2[i2][1]);
                float v2 = sub ? f2hi(s2[i2][2]) : f2lo(s2[i2][2]);
                float v3 = sub ? f2hi(s2[i2][3]) : f2lo(s2[i2][3]);
                if (mi.x == 0) v0 = -1e30f;
                if (mi.y == 0) v1 = -1e30f;
                if (mi.z == 0) v2 = -1e30f;
                if (mi.w == 0) v3 = -1e30f;
                float mx = fmaxf(fmaxf(v0, v1), fmaxf(v2, v3));
                mx = fmaxf(mx, __shfl_xor_sync(0xffffffffu, mx, 1));
                mx = fmaxf(mx, __shfl_xor_sync(0xffffffffu, mx, 2));
                mx = fmaxf(mx, __shfl_xor_sync(0xffffffffu, mx, 4));
                mx = fmaxf(mx, __shfl_xor_sync(0xffffffffu, mx, 8));
                float mnew = fmaxf(mrow[i], mx);
                float sc   = __expf(mrow[i] - mnew);
                mrow[i] = mnew;
                v0 = __expf(v0 - mnew);
                v1 = __expf(v1 - mnew);
                v2 = __expf(v2 - mnew);
                v3 = __expf(v3 - mnew);
                float rs = (v0 + v1) + (v2 + v3);
                rs += __shfl_xor_sync(0xffffffffu, rs, 1);
                rs += __shfl_xor_sync(0xffffffffu, rs, 2);
                rs += __shfl_xor_sync(0xffffffffu, rs, 4);
                rs += __shfl_xor_sync(0xffffffffu, rs, 8);
                lrow[i] = lrow[i] * sc + rs;
                u64 scd = dup2(sc);
                fmul2(o2[i][0], scd);
                fmul2(o2[i][1], scd);
                *(float4*)(Ps + (size_t)(r0 + i) * 68 + c0) = make_float4(v0, v1, v2, v3);
            }
        }
        __syncthreads();

        // ---- O += P V (col-pair packed; v pairs free from float4) ----
#pragma unroll 2
        for (int jm = 0; jm < 64; jm += 2) {
            ulonglong2 va = *(const ulonglong2*)(Vs + jm * 68 + c0);
            ulonglong2 vb = *(const ulonglong2*)(Vs + (jm + 1) * 68 + c0);
#pragma unroll
            for (int i = 0; i < 8; i++) {
                u64 pp = *(const u64*)(Ps + (size_t)(r0 + i) * 68 + jm);  // {P[r][jm],P[r][jm+1]} broadcast
                u64 p0 = dup2(f2lo(pp));
                u64 p1 = dup2(f2hi(pp));
                ffma2(o2[i][0], va.x, p0); ffma2(o2[i][1], va.y, p0);
                ffma2(o2[i][0], vb.x, p1); ffma2(o2[i][1], vb.y, p1);
            }
        }
    }

    // Write O[n][h*64 + v] = o / l
#pragma unroll
    for (int i = 0; i < 8; i++) {
        float inv = 1.0f / lrow[i];
        *(float4*)(g_O + (size_t)(n0 + r0 + i) * (HH * KD) + h * KD + c0) =
            make_float4(f2lo(o2[i][0]) * inv, f2hi(o2[i][0]) * inv,
                        f2lo(o2[i][1]) * inv, f2hi(o2[i][1]) * inv);
    }
}

// ---------------------------------------------------------------------------
extern "C" void kernel_launch(void* const* d_in, const int* in_sizes, int n_in,
                              void* d_out, int out_size)
{
    const float* X    = (const float*)d_in[0];
    const float* Mm   = (const float*)d_in[1];
    const int*   mask = (const int*)  d_in[2];
    const float* Wq   = (const float*)d_in[3];
    const float* Wk   = (const float*)d_in[4];
    const float* Wv   = (const float*)d_in[5];
    const float* Wo   = (const float*)d_in[6];
    float*       Y    = (float*)d_out;

    float *qp, *kp, *vp, *op;
    cudaGetSymbolAddress((void**)&qp, g_Q);
    cudaGetSymbolAddress((void**)&kp, g_K);
    cudaGetSymbolAddress((void**)&vp, g_V);
    cudaGetSymbolAddress((void**)&op, g_O);

    const int SMEM_ATTN = (64 * 132 + 64 * 68 + 64 * 68 + 128 * 68) * (int)sizeof(float);
    cudaFuncSetAttribute(attn_kernel, cudaFuncAttributeMaxDynamicSharedMemorySize, SMEM_ATTN);

    dim3 blk(256);
    // Q = X @ Wq_h   (per head h = blockIdx.y)
    gemm128x64<<<dim3(NN / 128, HH), blk>>>(X,  DD, Wq, (long)DD * KD, KD, qp, (long)NN * KD, KD, DD);
    // K = M @ Wk_h
    gemm128x64<<<dim3(MM / 128, HH), blk>>>(Mm, DD, Wk, (long)DD * KD, KD, kp, (long)MM * KD, KD, DD);
    // V = M @ Wv_h
    gemm128x64<<<dim3(MM / 128, HH), blk>>>(Mm, DD, Wv, (long)DD * KD, KD, vp, (long)MM * KD, KD, DD);
    // Attention (heads fastest -> mask tile L2 reuse)
    attn_kernel<<<dim3(HH, NN / 128), blk, SMEM_ATTN>>>(mask);
    // Y = O @ Wo_flat   (Wo [H,Vd,D] flat = [1024,1024]; blockIdx.y = 64-col block)
    gemm128x64<<<dim3(NN / 128, (HH * KD) / 64), blk>>>(op, HH * KD, Wo, (long)KD, HH * KD, Y, (long)KD, HH * KD, DD);
}

// round 6
// speedup vs baseline: 1.2312x; 1.0870x over previous
#include <cuda_runtime.h>
#include <cstddef>

#define HH 16
#define DD 1024
#define KD 64
#define NN 4096
#define MM 4096

// Scratch (__device__ globals: the allowed no-malloc workaround)
static __device__ float g_Q[(size_t)HH * NN * KD];   // [h][n][64]
static __device__ float g_K[(size_t)HH * MM * KD];   // [h][m][64]
static __device__ float g_V[(size_t)HH * MM * KD];   // [h][m][64]
static __device__ float g_O[(size_t)NN * (HH * KD)]; // [n][h*64+v]
static __device__ unsigned g_mbits[(size_t)NN * (MM / 32)]; // bit-packed mask (2MB)

typedef unsigned long long u64;

// ---- packed fp32x2 helpers (FFMA2 path: only reachable via PTX) ----------
__device__ __forceinline__ u64 dup2(float x) {
    u64 r; unsigned xi = __float_as_uint(x);
    asm("mov.b64 %0, {%1, %1};" : "=l"(r) : "r"(xi));
    return r;
}
__device__ __forceinline__ void ffma2(u64& d, u64 a, u64 b) {
    asm("fma.rn.f32x2 %0, %1, %2, %0;" : "+l"(d) : "l"(a), "l"(b));
}
__device__ __forceinline__ void fmul2(u64& d, u64 b) {
    asm("mul.rn.f32x2 %0, %0, %1;" : "+l"(d) : "l"(b));
}
__device__ __forceinline__ float f2lo(u64 v) { return __uint_as_float((unsigned)v); }
__device__ __forceinline__ float f2hi(u64 v) { return __uint_as_float((unsigned)(v >> 32)); }

// ---------------------------------------------------------------------------
// Bit-pack mask: one u32 word = 32 mask ints along m.
// ---------------------------------------------------------------------------
__global__ __launch_bounds__(256) void pack_mask(const int* __restrict__ mask,
                                                 unsigned* __restrict__ bits)
{
    int idx = blockIdx.x * 256 + threadIdx.x;        // 0 .. N*128-1
    const int* p = mask + (size_t)idx * 32;
    unsigned b = 0;
#pragma unroll
    for (int u = 0; u < 8; u++) {
        int4 m = ((const int4*)p)[u];
        b |= (unsigned)(m.x != 0) << (u * 4 + 0);
        b |= (unsigned)(m.y != 0) << (u * 4 + 1);
        b |= (unsigned)(m.z != 0) << (u * 4 + 2);
        b |= (unsigned)(m.w != 0) << (u * 4 + 3);
    }
    bits[idx] = b;
}

// ---------------------------------------------------------------------------
// Fused fp32 GEMM: C[128 x 128] = A[128 x K] * [W1 | W2] (two 64-wide panels).
// A tile transposed in smem with add-rotation (conflict-free scatter).
// Thread tile 8 rows x 8 cols, accumulators packed across row pairs (FFMA2).
// ---------------------------------------------------------------------------
__global__ __launch_bounds__(256) void gemm2(
    const float* __restrict__ A, int lda,
    const float* __restrict__ W1b, const float* __restrict__ W2b, long wStride, int ldw,
    float* __restrict__ C1b, float* __restrict__ C2b, long cStride, int ldc, int K)
{
    __shared__ float At[32 * 132];   // [kk][rotated row]
    __shared__ float Ws[32 * 136];   // [kk][128 cols: W1 | W2]

    const int tid = threadIdx.x;
    const int tx  = tid & 15;
    const int ty  = tid >> 4;
    const int c0  = tx * 8;          // 8 cols per thread
    const int r0  = ty * 8;          // 8 rows per thread
    const int row0 = blockIdx.x * 128;
    const float* W1 = W1b + (long)blockIdx.y * wStride;
    const float* W2 = W2b + (long)blockIdx.y * wStride;

    u64 acc[4][8];
#pragma unroll
    for (int i = 0; i < 4; i++)
#pragma unroll
        for (int j = 0; j < 8; j++) acc[i][j] = 0ull;

    for (int kt = 0; kt < K; kt += 32) {
        // A tile 128x32 -> transposed + rotated
#pragma unroll
        for (int u = 0; u < 4; u++) {
            int idx = tid + u * 256;
            int r   = idx >> 3;               // 0..127
            int kv  = idx & 7;                // 0..7
            float4 v = *(const float4*)(A + (size_t)(row0 + r) * lda + kt + kv * 4);
            int rr = (r + kv * 4) & 127;      // rotation: banks (20kv+4s+r) -> conflict-free
            At[(kv * 4 + 0) * 132 + rr] = v.x;
            At[(kv * 4 + 1) * 132 + rr] = v.y;
            At[(kv * 4 + 2) * 132 + rr] = v.z;
            At[(kv * 4 + 3) * 132 + rr] = v.w;
        }
        // W tiles 2 x (32x64)
#pragma unroll
        for (int u = 0; u < 4; u++) {
            int idx  = tid + u * 256;         // 0..1023
            int half = idx >> 9;
            int kk   = (idx >> 4) & 31;
            int cv   = idx & 15;
            const float* src = (half ? W2 : W1) + (size_t)(kt + kk) * ldw + cv * 4;
            *(float4*)(Ws + kk * 136 + half * 64 + cv * 4) = *(const float4*)src;
        }
        __syncthreads();

#pragma unroll 2
        for (int kk4 = 0; kk4 < 8; kk4++) {
            int ra = (r0 + kk4 * 4) & 127;          // rotated row start
            int rb = (r0 + 4 + kk4 * 4) & 127;
#pragma unroll
            for (int s = 0; s < 4; s++) {
                int kk = kk4 * 4 + s;
                ulonglong2 qa = *(const ulonglong2*)(At + kk * 132 + ra);  // rows r0..r0+3
                ulonglong2 qb = *(const ulonglong2*)(At + kk * 132 + rb);  // rows r0+4..r0+7
                float4 w0 = *(const float4*)(Ws + kk * 136 + c0);
                float4 w1 = *(const float4*)(Ws + kk * 136 + c0 + 4);
                u64 d0 = dup2(w0.x), d1 = dup2(w0.y), d2 = dup2(w0.z), d3 = dup2(w0.w);
                u64 d4 = dup2(w1.x), d5 = dup2(w1.y), d6 = dup2(w1.z), d7 = dup2(w1.w);
                ffma2(acc[0][0], qa.x, d0); ffma2(acc[0][1], qa.x, d1);
                ffma2(acc[0][2], qa.x, d2); ffma2(acc[0][3], qa.x, d3);
                ffma2(acc[0][4], qa.x, d4); ffma2(acc[0][5], qa.x, d5);
                ffma2(acc[0][6], qa.x, d6); ffma2(acc[0][7], qa.x, d7);
                ffma2(acc[1][0], qa.y, d0); ffma2(acc[1][1], qa.y, d1);
                ffma2(acc[1][2], qa.y, d2); ffma2(acc[1][3], qa.y, d3);
                ffma2(acc[1][4], qa.y, d4); ffma2(acc[1][5], qa.y, d5);
                ffma2(acc[1][6], qa.y, d6); ffma2(acc[1][7], qa.y, d7);
                ffma2(acc[2][0], qb.x, d0); ffma2(acc[2][1], qb.x, d1);
                ffma2(acc[2][2], qb.x, d2); ffma2(acc[2][3], qb.x, d3);
                ffma2(acc[2][4], qb.x, d4); ffma2(acc[2][5], qb.x, d5);
                ffma2(acc[2][6], qb.x, d6); ffma2(acc[2][7], qb.x, d7);
                ffma2(acc[3][0], qb.y, d0); ffma2(acc[3][1], qb.y, d1);
                ffma2(acc[3][2], qb.y, d2); ffma2(acc[3][3], qb.y, d3);
                ffma2(acc[3][4], qb.y, d4); ffma2(acc[3][5], qb.y, d5);
                ffma2(acc[3][6], qb.y, d6); ffma2(acc[3][7], qb.y, d7);
            }
        }
        __syncthreads();
    }

    // Epilogue: tx<8 -> C1 cols c0.., tx>=8 -> C2 cols c0-64..
    float* Cp = (tx < 8)
        ? (C1b + (long)blockIdx.y * cStride + c0)
        : (C2b + (long)blockIdx.y * cStride + (c0 - 64));
#pragma unroll
    for (int i2 = 0; i2 < 4; i2++) {
        float* rlo = Cp + (size_t)(row0 + r0 + 2 * i2) * ldc;
        float* rhi = Cp + (size_t)(row0 + r0 + 2 * i2 + 1) * ldc;
        *(float4*)(rlo)     = make_float4(f2lo(acc[i2][0]), f2lo(acc[i2][1]), f2lo(acc[i2][2]), f2lo(acc[i2][3]));
        *(float4*)(rlo + 4) = make_float4(f2lo(acc[i2][4]), f2lo(acc[i2][5]), f2lo(acc[i2][6]), f2lo(acc[i2][7]));
        *(float4*)(rhi)     = make_float4(f2hi(acc[i2][0]), f2hi(acc[i2][1]), f2hi(acc[i2][2]), f2hi(acc[i2][3]));
        *(float4*)(rhi + 4) = make_float4(f2hi(acc[i2][4]), f2hi(acc[i2][5]), f2hi(acc[i2][6]), f2hi(acc[i2][7]));
    }
}

// ---------------------------------------------------------------------------
// Flash attention fp32, BM=64 x BN=64, 256 threads, 3 CTAs/SM.
// Thread tile 4 rows x 4 cols. Q,K kd-major in smem (K rotated, 2-way max).
// QK^T packed across row pairs; PV packed across col pairs. Bit-packed mask
// prefetched into registers before QK.
// ---------------------------------------------------------------------------
__global__ __launch_bounds__(256, 3) void attn_kernel(void)
{
    extern __shared__ float sm[];
    float* Qt = sm;                  // [64 kd][68 rows]
    float* Kt = Qt + 64 * 68;        // [64 kd][68 rotated cols]
    float* Vs = Kt + 64 * 68;        // [64 jm][68 cols]
    float* Ps = Vs + 64 * 68;        // [64 row][68 cols]

    const int tid = threadIdx.x;
    const int tx  = tid & 15;
    const int ty  = tid >> 4;
    const int c0  = tx * 4;
    const int r0  = ty * 4;
    const int h   = blockIdx.x;      // heads fastest -> K/V + mask L2 reuse
    const int n0  = blockIdx.y * 64;
    const int shift = c0 & 31;

    const float* Qh = g_Q + (size_t)h * NN * KD;
    const float* Kh = g_K + (size_t)h * MM * KD;
    const float* Vh = g_V + (size_t)h * MM * KD;

    // Load Q tile 64x64, kd-major (one-time; unrotated)
#pragma unroll
    for (int u = 0; u < 4; u++) {
        int idx = tid + u * 256;     // 1024 float4 slots
        int r   = idx >> 4;          // 0..63
        int kv  = idx & 15;
        float4 v = *(const float4*)(Qh + (size_t)(n0 + r) * KD + kv * 4);
        Qt[(kv * 4 + 0) * 68 + r] = v.x;
        Qt[(kv * 4 + 1) * 68 + r] = v.y;
        Qt[(kv * 4 + 2) * 68 + r] = v.z;
        Qt[(kv * 4 + 3) * 68 + r] = v.w;
    }

    float mrow[4], lrow[4];
    u64 o2[4][2];
#pragma unroll
    for (int i = 0; i < 4; i++) {
        mrow[i] = -1e30f; lrow[i] = 0.0f;
        o2[i][0] = 0ull; o2[i][1] = 0ull;
    }

    for (int mt = 0; mt < MM; mt += 64) {
        __syncthreads();             // previous-tile readers of Kt/Vs/Ps done

        // Load K (kd-major, rotated) + V (row-major) 64x64 tiles
#pragma unroll
        for (int u = 0; u < 4; u++) {
            int idx = tid + u * 256;
            int j   = idx >> 4;      // 0..63
            int kv  = idx & 15;
            float4 kf = *(const float4*)(Kh + (size_t)(mt + j) * KD + kv * 4);
            int jr = (j + kv * 4) & 63;   // rotation: 8-way -> 2-way store conflicts
            Kt[(kv * 4 + 0) * 68 + jr] = kf.x;
            Kt[(kv * 4 + 1) * 68 + jr] = kf.y;
            Kt[(kv * 4 + 2) * 68 + jr] = kf.z;
            Kt[(kv * 4 + 3) * 68 + jr] = kf.w;
            *(float4*)(Vs + j * 68 + kv * 4) =
                *(const float4*)(Vh + (size_t)(mt + j) * KD + kv * 4);
        }

        // Prefetch mask bits (consumed after ~1000cyc of QK -> latency hidden)
        unsigned mw[4];
        {
            int widx = (mt + c0) >> 5;
#pragma unroll
            for (int i = 0; i < 4; i++)
                mw[i] = g_mbits[(size_t)(n0 + r0 + i) * (MM / 32) + widx];
        }
        __syncthreads();

        // ---- S = Q K^T (row-pair packed) ----
        u64 s2[2][4];
#pragma unroll
        for (int i = 0; i < 2; i++)
#pragma unroll
            for (int j = 0; j < 4; j++) s2[i][j] = 0ull;

#pragma unroll 4
        for (int kd4 = 0; kd4 < 16; kd4++) {
            int cc = (c0 + kd4 * 4) & 63;   // rotated col start
#pragma unroll
            for (int s = 0; s < 4; s++) {
                int kd = kd4 * 4 + s;
                ulonglong2 qa = *(const ulonglong2*)(Qt + kd * 68 + r0);  // rows r0..r0+3
                float4 kf = *(const float4*)(Kt + kd * 68 + cc);          // cols c0..c0+3
                u64 k0 = dup2(kf.x), k1 = dup2(kf.y), k2 = dup2(kf.z), k3 = dup2(kf.w);
                ffma2(s2[0][0], qa.x, k0); ffma2(s2[0][1], qa.x, k1);
                ffma2(s2[0][2], qa.x, k2); ffma2(s2[0][3], qa.x, k3);
                ffma2(s2[1][0], qa.y, k0); ffma2(s2[1][1], qa.y, k1);
                ffma2(s2[1][2], qa.y, k2); ffma2(s2[1][3], qa.y, k3);
            }
        }

        // ---- mask + online softmax ----
#pragma unroll
        for (int i = 0; i < 4; i++) {
            const int p = i >> 1, sub = i & 1;
            float v0 = sub ? f2hi(s2[p][0]) : f2lo(s2[p][0]);
            float v1 = sub ? f2hi(s2[p][1]) : f2lo(s2[p][1]);
            float v2 = sub ? f2hi(s2[p][2]) : f2lo(s2[p][2]);
            float v3 = sub ? f2hi(s2[p][3]) : f2lo(s2[p][3]);
            unsigned bits = (mw[i] >> shift) & 0xFu;
            if (!(bits & 1u)) v0 = -1e30f;
            if (!(bits & 2u)) v1 = -1e30f;
            if (!(bits & 4u)) v2 = -1e30f;
            if (!(bits & 8u)) v3 = -1e30f;
            float mx = fmaxf(fmaxf(v0, v1), fmaxf(v2, v3));
            mx = fmaxf(mx, __shfl_xor_sync(0xffffffffu, mx, 1));
            mx = fmaxf(mx, __shfl_xor_sync(0xffffffffu, mx, 2));
            mx = fmaxf(mx, __shfl_xor_sync(0xffffffffu, mx, 4));
            mx = fmaxf(mx, __shfl_xor_sync(0xffffffffu, mx, 8));
            float mnew = fmaxf(mrow[i], mx);
            float sc   = __expf(mrow[i] - mnew);
            mrow[i] = mnew;
            v0 = __expf(v0 - mnew);
            v1 = __expf(v1 - mnew);
            v2 = __expf(v2 - mnew);
            v3 = __expf(v3 - mnew);
            float rs = (v0 + v1) + (v2 + v3);
            rs += __shfl_xor_sync(0xffffffffu, rs, 1);
            rs += __shfl_xor_sync(0xffffffffu, rs, 2);
            rs += __shfl_xor_sync(0xffffffffu, rs, 4);
            rs += __shfl_xor_sync(0xffffffffu, rs, 8);
            lrow[i] = lrow[i] * sc + rs;
            u64 scd = dup2(sc);
            fmul2(o2[i][0], scd);
            fmul2(o2[i][1], scd);
            *(float4*)(Ps + (size_t)(r0 + i) * 68 + c0) = make_float4(v0, v1, v2, v3);
        }
        __syncthreads();

        // ---- O += P V (col-pair packed) ----
#pragma unroll 2
        for (int jm = 0; jm < 64; jm += 2) {
            ulonglong2 va = *(const ulonglong2*)(Vs + jm * 68 + c0);
            ulonglong2 vb = *(const ulonglong2*)(Vs + (jm + 1) * 68 + c0);
#pragma unroll
            for (int i = 0; i < 4; i++) {
                u64 pp = *(const u64*)(Ps + (size_t)(r0 + i) * 68 + jm);
                u64 p0 = dup2(f2lo(pp));
                u64 p1 = dup2(f2hi(pp));
                ffma2(o2[i][0], va.x, p0); ffma2(o2[i][1], va.y, p0);
                ffma2(o2[i][0], vb.x, p1); ffma2(o2[i][1], vb.y, p1);
            }
        }
    }

    // Write O[n][h*64 + v] = o / l
#pragma unroll
    for (int i = 0; i < 4; i++) {
        float inv = 1.0f / lrow[i];
        *(float4*)(g_O + (size_t)(n0 + r0 + i) * (HH * KD) + h * KD + c0) =
            make_float4(f2lo(o2[i][0]) * inv, f2hi(o2[i][0]) * inv,
                        f2lo(o2[i][1]) * inv, f2hi(o2[i][1]) * inv);
    }
}

// ---------------------------------------------------------------------------
extern "C" void kernel_launch(void* const* d_in, const int* in_sizes, int n_in,
                              void* d_out, int out_size)
{
    const float* X    = (const float*)d_in[0];
    const float* Mm   = (const float*)d_in[1];
    const int*   mask = (const int*)  d_in[2];
    const float* Wq   = (const float*)d_in[3];
    const float* Wk   = (const float*)d_in[4];
    const float* Wv   = (const float*)d_in[5];
    const float* Wo   = (const float*)d_in[6];
    float*       Y    = (float*)d_out;

    float *qp, *kp, *vp, *op;
    unsigned* mbp;
    cudaGetSymbolAddress((void**)&qp, g_Q);
    cudaGetSymbolAddress((void**)&kp, g_K);
    cudaGetSymbolAddress((void**)&vp, g_V);
    cudaGetSymbolAddress((void**)&op, g_O);
    cudaGetSymbolAddress((void**)&mbp, g_mbits);

    const int SMEM_ATTN = (4 * 64 * 68) * (int)sizeof(float);   // 69632 B
    cudaFuncSetAttribute(attn_kernel, cudaFuncAttributeMaxDynamicSharedMemorySize, SMEM_ATTN);

    dim3 blk(256);
    const long DK = (long)DD * KD, NK = (long)NN * KD, MK = (long)MM * KD;

    // Bit-pack mask: N*128 words
    pack_mask<<<(NN * (MM / 32)) / 256, blk>>>(mask, mbp);
    // Q: head pairs (2h, 2h+1) share the X tile
    gemm2<<<dim3(NN / 128, HH / 2), blk>>>(X, DD, Wq, Wq + DK, 2 * DK, KD,
                                           qp, qp + NK, 2 * NK, KD, DD);
    // K|V fused: same M tile feeds both projections of head h
    gemm2<<<dim3(MM / 128, HH), blk>>>(Mm, DD, Wk, Wv, DK, KD,
                                       kp, vp, MK, KD, DD);
    // Attention (heads fastest -> K/V + mask-bit L2 reuse)
    attn_kernel<<<dim3(HH, NN / 64), blk, SMEM_ATTN>>>();
    // Y = O @ Wo_flat: col-block pairs (128y, 128y+64)
    gemm2<<<dim3(NN / 128, (HH * KD) / 128), blk>>>(op, HH * KD, Wo, Wo + 64, 128, HH * KD,
                                                    Y, Y + 64, 128, HH * KD, DD);
}

// round 7
// speedup vs baseline: 1.2333x; 1.0017x over previous
#include <cuda_runtime.h>
#include <cstddef>

#define HH 16
#define DD 1024
#define KD 64
#define NN 4096
#define MM 4096

// Scratch (__device__ globals: the allowed no-malloc workaround)
static __device__ float g_Q[(size_t)HH * NN * KD];   // [h][n][64]
static __device__ float g_K[(size_t)HH * MM * KD];   // [h][m][64]
static __device__ float g_V[(size_t)HH * MM * KD];   // [h][m][64]
static __device__ float g_O[(size_t)NN * (HH * KD)]; // [n][h*64+v]
static __device__ unsigned g_mbits[(size_t)NN * (MM / 32)]; // bit-packed mask (2MB)

typedef unsigned long long u64;

// ---- packed fp32x2 helpers (FFMA2 path: only reachable via PTX) ----------
__device__ __forceinline__ u64 dup2(float x) {
    u64 r; unsigned xi = __float_as_uint(x);
    asm("mov.b64 %0, {%1, %1};" : "=l"(r) : "r"(xi));
    return r;
}
__device__ __forceinline__ void ffma2(u64& d, u64 a, u64 b) {
    asm("fma.rn.f32x2 %0, %1, %2, %0;" : "+l"(d) : "l"(a), "l"(b));
}
__device__ __forceinline__ void fmul2(u64& d, u64 b) {
    asm("mul.rn.f32x2 %0, %0, %1;" : "+l"(d) : "l"(b));
}
__device__ __forceinline__ float f2lo(u64 v) { return __uint_as_float((unsigned)v); }
__device__ __forceinline__ float f2hi(u64 v) { return __uint_as_float((unsigned)(v >> 32)); }

// ---------------------------------------------------------------------------
// Bit-pack mask: one u32 word = 32 mask ints along m.
// ---------------------------------------------------------------------------
__global__ __launch_bounds__(256) void pack_mask(const int* __restrict__ mask,
                                                 unsigned* __restrict__ bits)
{
    int idx = blockIdx.x * 256 + threadIdx.x;        // 0 .. N*128-1
    const int* p = mask + (size_t)idx * 32;
    unsigned b = 0;
#pragma unroll
    for (int u = 0; u < 8; u++) {
        int4 m = ((const int4*)p)[u];
        b |= (unsigned)(m.x != 0) << (u * 4 + 0);
        b |= (unsigned)(m.y != 0) << (u * 4 + 1);
        b |= (unsigned)(m.z != 0) << (u * 4 + 2);
        b |= (unsigned)(m.w != 0) << (u * 4 + 3);
    }
    bits[idx] = b;
}

// ---------------------------------------------------------------------------
// Fused fp32 GEMM: C[128 x 128] = A[128 x K] * [W1 | W2] (two 64-wide panels).
// A tile transposed in smem with add-rotation (conflict-free scatter).
// Thread tile 8 rows x 8 cols, accumulators packed across row pairs (FFMA2).
// ---------------------------------------------------------------------------
__global__ __launch_bounds__(256) void gemm2(
    const float* __restrict__ A, int lda,
    const float* __restrict__ W1b, const float* __restrict__ W2b, long wStride, int ldw,
    float* __restrict__ C1b, float* __restrict__ C2b, long cStride, int ldc, int K)
{
    __shared__ float At[32 * 132];   // [kk][rotated row]
    __shared__ float Ws[32 * 136];   // [kk][128 cols: W1 | W2]

    const int tid = threadIdx.x;
    const int tx  = tid & 15;
    const int ty  = tid >> 4;
    const int c0  = tx * 8;          // 8 cols per thread
    const int r0  = ty * 8;          // 8 rows per thread
    const int row0 = blockIdx.x * 128;
    const float* W1 = W1b + (long)blockIdx.y * wStride;
    const float* W2 = W2b + (long)blockIdx.y * wStride;

    u64 acc[4][8];
#pragma unroll
    for (int i = 0; i < 4; i++)
#pragma unroll
        for (int j = 0; j < 8; j++) acc[i][j] = 0ull;

    for (int kt = 0; kt < K; kt += 32) {
        // A tile 128x32 -> transposed + rotated
#pragma unroll
        for (int u = 0; u < 4; u++) {
            int idx = tid + u * 256;
            int r   = idx >> 3;               // 0..127
            int kv  = idx & 7;                // 0..7
            float4 v = *(const float4*)(A + (size_t)(row0 + r) * lda + kt + kv * 4);
            int rr = (r + kv * 4) & 127;      // rotation: banks (20kv+4s+r) -> conflict-free
            At[(kv * 4 + 0) * 132 + rr] = v.x;
            At[(kv * 4 + 1) * 132 + rr] = v.y;
            At[(kv * 4 + 2) * 132 + rr] = v.z;
            At[(kv * 4 + 3) * 132 + rr] = v.w;
        }
        // W tiles 2 x (32x64)
#pragma unroll
        for (int u = 0; u < 4; u++) {
            int idx  = tid + u * 256;         // 0..1023
            int half = idx >> 9;
            int kk   = (idx >> 4) & 31;
            int cv   = idx & 15;
            const float* src = (half ? W2 : W1) + (size_t)(kt + kk) * ldw + cv * 4;
            *(float4*)(Ws + kk * 136 + half * 64 + cv * 4) = *(const float4*)src;
        }
        __syncthreads();

#pragma unroll 2
        for (int kk4 = 0; kk4 < 8; kk4++) {
            int ra = (r0 + kk4 * 4) & 127;          // rotated row start
            int rb = (r0 + 4 + kk4 * 4) & 127;
#pragma unroll
            for (int s = 0; s < 4; s++) {
                int kk = kk4 * 4 + s;
                ulonglong2 qa = *(const ulonglong2*)(At + kk * 132 + ra);  // rows r0..r0+3
                ulonglong2 qb = *(const ulonglong2*)(At + kk * 132 + rb);  // rows r0+4..r0+7
                float4 w0 = *(const float4*)(Ws + kk * 136 + c0);
                float4 w1 = *(const float4*)(Ws + kk * 136 + c0 + 4);
                u64 d0 = dup2(w0.x), d1 = dup2(w0.y), d2 = dup2(w0.z), d3 = dup2(w0.w);
                u64 d4 = dup2(w1.x), d5 = dup2(w1.y), d6 = dup2(w1.z), d7 = dup2(w1.w);
                ffma2(acc[0][0], qa.x, d0); ffma2(acc[0][1], qa.x, d1);
                ffma2(acc[0][2], qa.x, d2); ffma2(acc[0][3], qa.x, d3);
                ffma2(acc[0][4], qa.x, d4); ffma2(acc[0][5], qa.x, d5);
                ffma2(acc[0][6], qa.x, d6); ffma2(acc[0][7], qa.x, d7);
                ffma2(acc[1][0], qa.y, d0); ffma2(acc[1][1], qa.y, d1);
                ffma2(acc[1][2], qa.y, d2); ffma2(acc[1][3], qa.y, d3);
                ffma2(acc[1][4], qa.y, d4); ffma2(acc[1][5], qa.y, d5);
                ffma2(acc[1][6], qa.y, d6); ffma2(acc[1][7], qa.y, d7);
                ffma2(acc[2][0], qb.x, d0); ffma2(acc[2][1], qb.x, d1);
                ffma2(acc[2][2], qb.x, d2); ffma2(acc[2][3], qb.x, d3);
                ffma2(acc[2][4], qb.x, d4); ffma2(acc[2][5], qb.x, d5);
                ffma2(acc[2][6], qb.x, d6); ffma2(acc[2][7], qb.x, d7);
                ffma2(acc[3][0], qb.y, d0); ffma2(acc[3][1], qb.y, d1);
                ffma2(acc[3][2], qb.y, d2); ffma2(acc[3][3], qb.y, d3);
                ffma2(acc[3][4], qb.y, d4); ffma2(acc[3][5], qb.y, d5);
                ffma2(acc[3][6], qb.y, d6); ffma2(acc[3][7], qb.y, d7);
            }
        }
        __syncthreads();
    }

    // Epilogue: tx<8 -> C1 cols c0.., tx>=8 -> C2 cols c0-64..
    float* Cp = (tx < 8)
        ? (C1b + (long)blockIdx.y * cStride + c0)
        : (C2b + (long)blockIdx.y * cStride + (c0 - 64));
#pragma unroll
    for (int i2 = 0; i2 < 4; i2++) {
        float* rlo = Cp + (size_t)(row0 + r0 + 2 * i2) * ldc;
        float* rhi = Cp + (size_t)(row0 + r0 + 2 * i2 + 1) * ldc;
        *(float4*)(rlo)     = make_float4(f2lo(acc[i2][0]), f2lo(acc[i2][1]), f2lo(acc[i2][2]), f2lo(acc[i2][3]));
        *(float4*)(rlo + 4) = make_float4(f2lo(acc[i2][4]), f2lo(acc[i2][5]), f2lo(acc[i2][6]), f2lo(acc[i2][7]));
        *(float4*)(rhi)     = make_float4(f2hi(acc[i2][0]), f2hi(acc[i2][1]), f2hi(acc[i2][2]), f2hi(acc[i2][3]));
        *(float4*)(rhi + 4) = make_float4(f2hi(acc[i2][4]), f2hi(acc[i2][5]), f2hi(acc[i2][6]), f2hi(acc[i2][7]));
    }
}

// ---------------------------------------------------------------------------
// Flash attention fp32, BM=64 x BN=64, 256 threads, 3 CTAs/SM.
// Thread tile 4 rows x 4 cols. Q,K kd-major in smem (K rotated, 2-way max).
// QK^T packed across row pairs; PV packed across col pairs. Bit-packed mask
// prefetched into registers before QK.
// ---------------------------------------------------------------------------
__global__ __launch_bounds__(256, 3) void attn_kernel(void)
{
    extern __shared__ float sm[];
    float* Qt = sm;                  // [64 kd][68 rows]
    float* Kt = Qt + 64 * 68;        // [64 kd][68 rotated cols]
    float* Vs = Kt + 64 * 68;        // [64 jm][68 cols]
    float* Ps = Vs + 64 * 68;        // [64 row][68 cols]

    const int tid = threadIdx.x;
    const int tx  = tid & 15;
    const int ty  = tid >> 4;
    const int c0  = tx * 4;
    const int r0  = ty * 4;
    const int h   = blockIdx.x;      // heads fastest -> K/V + mask L2 reuse
    const int n0  = blockIdx.y * 64;
    const int shift = c0 & 31;

    const float* Qh = g_Q + (size_t)h * NN * KD;
    const float* Kh = g_K + (size_t)h * MM * KD;
    const float* Vh = g_V + (size_t)h * MM * KD;

    // Load Q tile 64x64, kd-major (one-time; unrotated)
#pragma unroll
    for (int u = 0; u < 4; u++) {
        int idx = tid + u * 256;     // 1024 float4 slots
        int r   = idx >> 4;          // 0..63
        int kv  = idx & 15;
        float4 v = *(const float4*)(Qh + (size_t)(n0 + r) * KD + kv * 4);
        Qt[(kv * 4 + 0) * 68 + r] = v.x;
        Qt[(kv * 4 + 1) * 68 + r] = v.y;
        Qt[(kv * 4 + 2) * 68 + r] = v.z;
        Qt[(kv * 4 + 3) * 68 + r] = v.w;
    }

    float mrow[4], lrow[4];
    u64 o2[4][2];
#pragma unroll
    for (int i = 0; i < 4; i++) {
        mrow[i] = -1e30f; lrow[i] = 0.0f;
        o2[i][0] = 0ull; o2[i][1] = 0ull;
    }

    for (int mt = 0; mt < MM; mt += 64) {
        __syncthreads();             // previous-tile readers of Kt/Vs/Ps done

        // Load K (kd-major, rotated) + V (row-major) 64x64 tiles
#pragma unroll
        for (int u = 0; u < 4; u++) {
            int idx = tid + u * 256;
            int j   = idx >> 4;      // 0..63
            int kv  = idx & 15;
            float4 kf = *(const float4*)(Kh + (size_t)(mt + j) * KD + kv * 4);
            int jr = (j + kv * 4) & 63;   // rotation: 8-way -> 2-way store conflicts
            Kt[(kv * 4 + 0) * 68 + jr] = kf.x;
            Kt[(kv * 4 + 1) * 68 + jr] = kf.y;
            Kt[(kv * 4 + 2) * 68 + jr] = kf.z;
            Kt[(kv * 4 + 3) * 68 + jr] = kf.w;
            *(float4*)(Vs + j * 68 + kv * 4) =
                *(const float4*)(Vh + (size_t)(mt + j) * KD + kv * 4);
        }

        // Prefetch mask bits (consumed after ~1000cyc of QK -> latency hidden)
        unsigned mw[4];
        {
            int widx = (mt + c0) >> 5;
#pragma unroll
            for (int i = 0; i < 4; i++)
                mw[i] = g_mbits[(size_t)(n0 + r0 + i) * (MM / 32) + widx];
        }
        __syncthreads();

        // ---- S = Q K^T (row-pair packed) ----
        u64 s2[2][4];
#pragma unroll
        for (int i = 0; i < 2; i++)
#pragma unroll
            for (int j = 0; j < 4; j++) s2[i][j] = 0ull;

#pragma unroll 4
        for (int kd4 = 0; kd4 < 16; kd4++) {
            int cc = (c0 + kd4 * 4) & 63;   // rotated col start
#pragma unroll
            for (int s = 0; s < 4; s++) {
                int kd = kd4 * 4 + s;
                ulonglong2 qa = *(const ulonglong2*)(Qt + kd * 68 + r0);  // rows r0..r0+3
                float4 kf = *(const float4*)(Kt + kd * 68 + cc);          // cols c0..c0+3
                u64 k0 = dup2(kf.x), k1 = dup2(kf.y), k2 = dup2(kf.z), k3 = dup2(kf.w);
                ffma2(s2[0][0], qa.x, k0); ffma2(s2[0][1], qa.x, k1);
                ffma2(s2[0][2], qa.x, k2); ffma2(s2[0][3], qa.x, k3);
                ffma2(s2[1][0], qa.y, k0); ffma2(s2[1][1], qa.y, k1);
                ffma2(s2[1][2], qa.y, k2); ffma2(s2[1][3], qa.y, k3);
            }
        }

        // ---- mask + online softmax ----
#pragma unroll
        for (int i = 0; i < 4; i++) {
            const int p = i >> 1, sub = i & 1;
            float v0 = sub ? f2hi(s2[p][0]) : f2lo(s2[p][0]);
            float v1 = sub ? f2hi(s2[p][1]) : f2lo(s2[p][1]);
            float v2 = sub ? f2hi(s2[p][2]) : f2lo(s2[p][2]);
            float v3 = sub ? f2hi(s2[p][3]) : f2lo(s2[p][3]);
            unsigned bits = (mw[i] >> shift) & 0xFu;
            if (!(bits & 1u)) v0 = -1e30f;
            if (!(bits & 2u)) v1 = -1e30f;
            if (!(bits & 4u)) v2 = -1e30f;
            if (!(bits & 8u)) v3 = -1e30f;
            float mx = fmaxf(fmaxf(v0, v1), fmaxf(v2, v3));
            mx = fmaxf(mx, __shfl_xor_sync(0xffffffffu, mx, 1));
            mx = fmaxf(mx, __shfl_xor_sync(0xffffffffu, mx, 2));
            mx = fmaxf(mx, __shfl_xor_sync(0xffffffffu, mx, 4));
            mx = fmaxf(mx, __shfl_xor_sync(0xffffffffu, mx, 8));
            float mnew = fmaxf(mrow[i], mx);
            float sc   = __expf(mrow[i] - mnew);
            mrow[i] = mnew;
            v0 = __expf(v0 - mnew);
            v1 = __expf(v1 - mnew);
            v2 = __expf(v2 - mnew);
            v3 = __expf(v3 - mnew);
            float rs = (v0 + v1) + (v2 + v3);
            rs += __shfl_xor_sync(0xffffffffu, rs, 1);
            rs += __shfl_xor_sync(0xffffffffu, rs, 2);
            rs += __shfl_xor_sync(0xffffffffu, rs, 4);
            rs += __shfl_xor_sync(0xffffffffu, rs, 8);
            lrow[i] = lrow[i] * sc + rs;
            u64 scd = dup2(sc);
            fmul2(o2[i][0], scd);
            fmul2(o2[i][1], scd);
            *(float4*)(Ps + (size_t)(r0 + i) * 68 + c0) = make_float4(v0, v1, v2, v3);
        }
        __syncthreads();

        // ---- O += P V (col-pair packed) ----
#pragma unroll 2
        for (int jm = 0; jm < 64; jm += 2) {
            ulonglong2 va = *(const ulonglong2*)(Vs + jm * 68 + c0);
            ulonglong2 vb = *(const ulonglong2*)(Vs + (jm + 1) * 68 + c0);
#pragma unroll
            for (int i = 0; i < 4; i++) {
                u64 pp = *(const u64*)(Ps + (size_t)(r0 + i) * 68 + jm);
                u64 p0 = dup2(f2lo(pp));
                u64 p1 = dup2(f2hi(pp));
                ffma2(o2[i][0], va.x, p0); ffma2(o2[i][1], va.y, p0);
                ffma2(o2[i][0], vb.x, p1); ffma2(o2[i][1], vb.y, p1);
            }
        }
    }

    // Write O[n][h*64 + v] = o / l
#pragma unroll
    for (int i = 0; i < 4; i++) {
        float inv = 1.0f / lrow[i];
        *(float4*)(g_O + (size_t)(n0 + r0 + i) * (HH * KD) + h * KD + c0) =
            make_float4(f2lo(o2[i][0]) * inv, f2hi(o2[i][0]) * inv,
                        f2lo(o2[i][1]) * inv, f2hi(o2[i][1]) * inv);
    }
}

// ---------------------------------------------------------------------------
extern "C" void kernel_launch(void* const* d_in, const int* in_sizes, int n_in,
                              void* d_out, int out_size)
{
    const float* X    = (const float*)d_in[0];
    const float* Mm   = (const float*)d_in[1];
    const int*   mask = (const int*)  d_in[2];
    const float* Wq   = (const float*)d_in[3];
    const float* Wk   = (const float*)d_in[4];
    const float* Wv   = (const float*)d_in[5];
    const float* Wo   = (const float*)d_in[6];
    float*       Y    = (float*)d_out;

    float *qp, *kp, *vp, *op;
    unsigned* mbp;
    cudaGetSymbolAddress((void**)&qp, g_Q);
    cudaGetSymbolAddress((void**)&kp, g_K);
    cudaGetSymbolAddress((void**)&vp, g_V);
    cudaGetSymbolAddress((void**)&op, g_O);
    cudaGetSymbolAddress((void**)&mbp, g_mbits);

    const int SMEM_ATTN = (4 * 64 * 68) * (int)sizeof(float);   // 69632 B
    cudaFuncSetAttribute(attn_kernel, cudaFuncAttributeMaxDynamicSharedMemorySize, SMEM_ATTN);

    dim3 blk(256);
    const long DK = (long)DD * KD, NK = (long)NN * KD, MK = (long)MM * KD;

    // Bit-pack mask: N*128 words
    pack_mask<<<(NN * (MM / 32)) / 256, blk>>>(mask, mbp);
    // Q: head pairs (2h, 2h+1) share the X tile
    gemm2<<<dim3(NN / 128, HH / 2), blk>>>(X, DD, Wq, Wq + DK, 2 * DK, KD,
                                           qp, qp + NK, 2 * NK, KD, DD);
    // K|V fused: same M tile feeds both projections of head h
    gemm2<<<dim3(MM / 128, HH), blk>>>(Mm, DD, Wk, Wv, DK, KD,
                                       kp, vp, MK, KD, DD);
    // Attention (heads fastest -> K/V + mask-bit L2 reuse)
    attn_kernel<<<dim3(HH, NN / 64), blk, SMEM_ATTN>>>();
    // Y = O @ Wo_flat: col-block pairs (128y, 128y+64)
    gemm2<<<dim3(NN / 128, (HH * KD) / 128), blk>>>(op, HH * KD, Wo, Wo + 64, 128, HH * KD,
                                                    Y, Y + 64, 128, HH * KD, DD);
}